// round 9
// baseline (speedup 1.0000x reference)
#include <cuda_runtime.h>
#include <math.h>
#include <float.h>
#include <stdint.h>

// MoE gate: logits = hidden @ gate^T ; softmax over 8 experts; top-2; renormalize.
// hidden: [T, 4096] f32 (T = 16384), gate: [8, 4096] f32.
// Output (flattened f32): [T*2] topk weights, then [T*2] expert indices (as float).
//
// R7 compute core (packed fma.rn.f32x2, quad-deduplicated packed-gate loads)
// with the x stream moved to a cp.async (LDGSTS) 4-stage smem ring: ~12KB in
// flight per block at zero register cost, fixing the latency-bound stall that
// register ping-pong (R5/R7, DRAM stuck ~50%) could not.

#define NEXP   8
#define HDIM   4096
#define HV     (HDIM / 4)      // 1024 float4 per row
#define HSPLIT 2
#define HHV    (HV / HSPLIT)   // 512 float4 per half
#define ITERS  (HHV / 8)       // 64 iters (8 float4 of h per half per iter)
#define NTILES (HV / 8)        // 128 one-KB gate tiles
#define TOK_PER_BLOCK 16
#define NSTAGE 4               // cp.async ring depth (4KB per stage)

// Packed gate: tile t (8 float4 of h), chunk (i,j) = float4 of expert values
//   s = i>>1, epb = (i&1)*2, h = (t*8+j)*4 + s
//   chunk = ( g[2epb][h], g[2epb+1][h], g[2epb+2][h], g[2epb+3][h] )
__device__ float4 g_packed[NTILES * 64];   // 128 KB

__global__ void pack_gate_kernel(const float* __restrict__ gate)
{
    const int tid = blockIdx.x * blockDim.x + threadIdx.x;
    if (tid >= NTILES * 64) return;
    const int t = tid >> 6, r = tid & 63, i = r >> 3, j = r & 7;
    const int s = i >> 1, epb = (i & 1) * 2;
    const int h = (t * 8 + j) * 4 + s;
    float4 v;
    v.x = gate[(2 * epb + 0) * HDIM + h];
    v.y = gate[(2 * epb + 1) * HDIM + h];
    v.z = gate[(2 * epb + 2) * HDIM + h];
    v.w = gate[(2 * epb + 3) * HDIM + h];
    g_packed[t * 64 + i * 8 + j] = v;
}

#define FMA2(acc, a, b) \
    asm("fma.rn.f32x2 %0, %1, %2, %0;" : "+l"(acc) : "l"(a), "l"(b))
#define ADD2(d, a, b) \
    asm("add.rn.f32x2 %0, %1, %2;" : "=l"(d) : "l"(a), "l"(b))
#define PACK_DUP2(o, f) \
    asm("mov.b64 %0, {%1, %1};" : "=l"(o) : "r"(__float_as_uint(f)))
#define UNPACK2(lo, hi, v) \
    asm("mov.b64 {%0, %1}, %2;" : "=r"(lo), "=r"(hi) : "l"(v))

// FFMA2 burst: 2 tokens x 4 h-scalars x 4 expert-pairs
#define COMPUTE(xv0, xv1, it)                                                  \
    do {                                                                       \
        const ulonglong2* gt = gpk + ((size_t)(tile0 + (it))) * 64 + j;        \
        const float* xf0 = &(xv0).x;                                           \
        const float* xf1 = &(xv1).x;                                           \
        _Pragma("unroll")                                                      \
        for (int sc = 0; sc < 4; sc++) {                                       \
            const ulonglong2 gA = gt[(2 * sc) * 8];                            \
            const ulonglong2 gB = gt[(2 * sc + 1) * 8];                        \
            uint64_t p0, p1;                                                   \
            PACK_DUP2(p0, xf0[sc]);                                            \
            PACK_DUP2(p1, xf1[sc]);                                            \
            FMA2(acc[0][0], p0, gA.x); FMA2(acc[0][1], p0, gA.y);              \
            FMA2(acc[0][2], p0, gB.x); FMA2(acc[0][3], p0, gB.y);              \
            FMA2(acc[1][0], p1, gA.x); FMA2(acc[1][1], p1, gA.y);              \
            FMA2(acc[1][2], p1, gB.x); FMA2(acc[1][3], p1, gB.y);              \
        }                                                                      \
    } while (0)

// Producer: stage 'slot' <- 4KB chunk 'itc' (16 tokens x 2 halves x 128B).
// 256 chunks of 16B, 2 per thread; consecutive tids sweep j then token
// -> 128B-line coalesced. Guarded issue; commit is UNCONDITIONAL so group
// numbering stays: group g == chunk g (prologue 0..2, iter k -> chunk k+3).
#define ISSUE(slot, itc)                                                          \
    do {                                                                          \
        if ((itc) < ITERS) {                                                      \
            _Pragma("unroll")                                                     \
            for (int rr = 0; rr < 2; rr++) {                                      \
                const int idx = threadIdx.x + rr * 128;                           \
                const int hf = idx >> 7, rem = idx & 127;                         \
                const int tk = rem >> 3, jj = rem & 7;                            \
                const float4* src = hid + (size_t)(tok_base + tk) * HV            \
                                      + hf * HHV + (itc) * 8 + jj;                \
                const uint32_t dst = (uint32_t)__cvta_generic_to_shared(          \
                    &stage[slot][hf][tk][jj]);                                    \
                asm volatile("cp.async.cg.shared.global [%0], [%1], 16;"          \
                             :: "r"(dst), "l"(src));                              \
            }                                                                     \
        }                                                                         \
        asm volatile("cp.async.commit_group;");                                   \
    } while (0)

__global__ __launch_bounds__(128, 8) void moe_gate_kernel(
    const float4* __restrict__ hid,
    float* __restrict__ out,
    int n_tokens)
{
    __shared__ float4 stage[NSTAGE][HSPLIT][TOK_PER_BLOCK / 2 * 2][8]; // [4][2][16][8] = 16KB
    __shared__ float  part[2][HSPLIT][8][NEXP];

    const int lane = threadIdx.x & 31;
    const int w    = threadIdx.x >> 5;   // 0..3
    const int tw   = w >> 1;             // token warp 0..1 (8 tokens each)
    const int half = w & 1;              // h-half
    const int grp  = lane >> 3;          // 0..3
    const int j    = lane & 7;           // h-sub position

    const int tok_base = blockIdx.x * TOK_PER_BLOCK;
    if (tok_base >= n_tokens) return;

    const ulonglong2* gpk = (const ulonglong2*)g_packed;
    const int tile0 = half * (HHV / 8);  // 64 gate tiles per half

    uint64_t acc[2][4];
    #pragma unroll
    for (int t = 0; t < 2; t++)
        #pragma unroll
        for (int ep = 0; ep < 4; ep++)
            acc[t][ep] = 0ull;

    // prologue: stages 0..NSTAGE-2 (groups 0..2 == chunks 0..2)
    #pragma unroll
    for (int s = 0; s < NSTAGE - 1; s++)
        ISSUE(s, s);

    const int tk0 = tw * 8 + grp * 2;

    #pragma unroll 1
    for (int it = 0; it < ITERS; it++) {
        // stage 'it' == group 'it'; groups issued so far = 3 + it
        asm volatile("cp.async.wait_group %0;" :: "n"(NSTAGE - 2));
        __syncthreads();

        const int sl = it & (NSTAGE - 1);
        const float4 xv0 = stage[sl][half][tk0 + 0][j];
        const float4 xv1 = stage[sl][half][tk0 + 1][j];
        COMPUTE(xv0, xv1, it);

        // refill slot (it-1)%NSTAGE with chunk it+NSTAGE-1 (all warps are past
        // their reads of stage it-1: they happened before this iter's barrier)
        ISSUE((it + NSTAGE - 1) & (NSTAGE - 1), it + NSTAGE - 1);
    }

    // reduce over the 8 j-lanes of each grp (masks 1,2,4 stay within the grp)
    #pragma unroll
    for (int t = 0; t < 2; t++)
        #pragma unroll
        for (int ep = 0; ep < 4; ep++) {
            uint64_t v = acc[t][ep], o;
            o = __shfl_xor_sync(0xffffffffu, (unsigned long long)v, 1); ADD2(v, v, o);
            o = __shfl_xor_sync(0xffffffffu, (unsigned long long)v, 2); ADD2(v, v, o);
            o = __shfl_xor_sync(0xffffffffu, (unsigned long long)v, 4); ADD2(v, v, o);
            acc[t][ep] = v;
        }

    if (j == 0) {
        #pragma unroll
        for (int t = 0; t < 2; t++)
            #pragma unroll
            for (int ep = 0; ep < 4; ep++) {
                unsigned lo, hi;
                UNPACK2(lo, hi, acc[t][ep]);
                part[tw][half][grp * 2 + t][2 * ep + 0] = __uint_as_float(lo);
                part[tw][half][grp * 2 + t][2 * ep + 1] = __uint_as_float(hi);
            }
    }
    __syncthreads();

    // finalize: half-0 warps, lanes 0..7 -> one token each
    if (half == 0 && lane < 8) {
        const int token = tok_base + tw * 8 + lane;

        float l[NEXP];
        #pragma unroll
        for (int q = 0; q < NEXP; q++)
            l[q] = part[tw][0][lane][q] + part[tw][1][lane][q];

        // top-1 (strict > keeps lowest index on ties, matching lax.top_k)
        float b0 = l[0]; int i0 = 0;
        #pragma unroll
        for (int q = 1; q < NEXP; q++)
            if (l[q] > b0) { b0 = l[q]; i0 = q; }

        // top-2
        float b1 = -FLT_MAX; int i1 = 0;
        #pragma unroll
        for (int q = 0; q < NEXP; q++)
            if (q != i0 && l[q] > b1) { b1 = l[q]; i1 = q; }

        // renormalized top-2 softmax: w0 = e^{l0} / (e^{l0} + e^{l1})
        const float w0 = 1.0f / (1.0f + expf(b1 - b0));
        const float w1 = 1.0f - w0;

        float* out_idx = out + (size_t)n_tokens * 2;
        out[token * 2 + 0] = w0;
        out[token * 2 + 1] = w1;
        out_idx[token * 2 + 0] = (float)i0;
        out_idx[token * 2 + 1] = (float)i1;
    }
}

extern "C" void kernel_launch(void* const* d_in, const int* in_sizes, int n_in,
                              void* d_out, int out_size)
{
    const float* hid  = (const float*)d_in[0];   // hidden_states
    const float* gate = (const float*)d_in[1];   // gate_weight
    float* out = (float*)d_out;

    const int n_tokens = in_sizes[0] / HDIM;     // 16384

    pack_gate_kernel<<<(NTILES * 64 + 255) / 256, 256>>>(gate);

    const int blocks = (n_tokens + TOK_PER_BLOCK - 1) / TOK_PER_BLOCK;  // 1024
    moe_gate_kernel<<<blocks, 128>>>((const float4*)hid, out, n_tokens);
}

// round 12
// speedup vs baseline: 1.1016x; 1.1016x over previous
#include <cuda_runtime.h>
#include <math.h>
#include <float.h>
#include <stdint.h>

// MoE gate: logits = hidden @ gate^T ; softmax over 8 experts; top-2; renormalize.
// hidden: [T, 4096] f32 (T = 16384), gate: [8, 4096] f32.
// Output (flattened f32): [T*2] topk weights, then [T*2] expert indices (as float).
//
// R7 compute core (packed fma.rn.f32x2, quad-deduplicated packed-gate loads)
// + per-WARP-private cp.async rings (depth 4, 1KB/stage). The lane that issues
// each 16B copy is the lane that reads it back, so cp.async.wait_group alone
// gives visibility: NO block barriers in the main loop (R8's mistake), and
// ~3KB continuously in flight per warp regardless of L1tex queue latency
// (R5/R7's register ping-pong only covered ~600cyc of an effectively ~1500cyc
// queue-inflated latency).

#define NEXP   8
#define HDIM   4096
#define HV     (HDIM / 4)      // 1024 float4 per row
#define HSPLIT 2
#define HHV    (HV / HSPLIT)   // 512 float4 per half
#define ITERS  (HHV / 8)       // 64 iters (8 float4 of h per half per iter)
#define NTILES (HV / 8)        // 128 one-KB gate tiles
#define TOK_PER_BLOCK 16
#define NSTAGE 4               // per-warp ring depth (1KB per stage)

// Packed gate: tile t (8 float4 of h), chunk (i,j) = float4 of expert values
//   s = i>>1, epb = (i&1)*2, h = (t*8+j)*4 + s
//   chunk = ( g[2epb][h], g[2epb+1][h], g[2epb+2][h], g[2epb+3][h] )
__device__ float4 g_packed[NTILES * 64];   // 128 KB

__global__ void pack_gate_kernel(const float* __restrict__ gate)
{
    const int tid = blockIdx.x * blockDim.x + threadIdx.x;
    if (tid >= NTILES * 64) return;
    const int t = tid >> 6, r = tid & 63, i = r >> 3, j = r & 7;
    const int s = i >> 1, epb = (i & 1) * 2;
    const int h = (t * 8 + j) * 4 + s;
    float4 v;
    v.x = gate[(2 * epb + 0) * HDIM + h];
    v.y = gate[(2 * epb + 1) * HDIM + h];
    v.z = gate[(2 * epb + 2) * HDIM + h];
    v.w = gate[(2 * epb + 3) * HDIM + h];
    g_packed[t * 64 + i * 8 + j] = v;
}

#define FMA2(acc, a, b) \
    asm("fma.rn.f32x2 %0, %1, %2, %0;" : "+l"(acc) : "l"(a), "l"(b))
#define ADD2(d, a, b) \
    asm("add.rn.f32x2 %0, %1, %2;" : "=l"(d) : "l"(a), "l"(b))
#define PACK_DUP2(o, f) \
    asm("mov.b64 %0, {%1, %1};" : "=l"(o) : "r"(__float_as_uint(f)))
#define UNPACK2(lo, hi, v) \
    asm("mov.b64 {%0, %1}, %2;" : "=r"(lo), "=r"(hi) : "l"(v))

// FFMA2 burst: 2 tokens x 4 h-scalars x 4 expert-pairs
#define COMPUTE(xv0, xv1, it)                                                  \
    do {                                                                       \
        const ulonglong2* gt = gpk + ((size_t)(tile0 + (it))) * 64 + j;        \
        const float* xf0 = &(xv0).x;                                           \
        const float* xf1 = &(xv1).x;                                           \
        _Pragma("unroll")                                                      \
        for (int sc = 0; sc < 4; sc++) {                                       \
            const ulonglong2 gA = gt[(2 * sc) * 8];                            \
            const ulonglong2 gB = gt[(2 * sc + 1) * 8];                        \
            uint64_t p0, p1;                                                   \
            PACK_DUP2(p0, xf0[sc]);                                            \
            PACK_DUP2(p1, xf1[sc]);                                            \
            FMA2(acc[0][0], p0, gA.x); FMA2(acc[0][1], p0, gA.y);              \
            FMA2(acc[0][2], p0, gB.x); FMA2(acc[0][3], p0, gB.y);              \
            FMA2(acc[1][0], p1, gA.x); FMA2(acc[1][1], p1, gA.y);              \
            FMA2(acc[1][2], p1, gB.x); FMA2(acc[1][3], p1, gB.y);              \
        }                                                                      \
    } while (0)

// Per-warp issue of chunk 'itc' into ring stage 'slot'. Lane (grp,j) copies
// its OWN tokens (grp*2, grp*2+1) at its OWN j -> issuer == reader, so
// wait_group alone synchronizes. 2 x 16B cp.async per lane; per warp
// instruction = 4 x 128B lines (same coalescing as LDG.128 path).
// Commit is UNCONDITIONAL so per-thread group numbering stays: group g == chunk g.
#define ISSUE(slot, itc)                                                       \
    do {                                                                       \
        if ((itc) < ITERS) {                                                   \
            const float4* s0 = xsrc + (size_t)(itc) * 8;                       \
            asm volatile("cp.async.cg.shared.global [%0], [%1], 16;"           \
                         :: "r"(dstb + (slot) * 1024u), "l"(s0));              \
            asm volatile("cp.async.cg.shared.global [%0], [%1], 16;"           \
                         :: "r"(dstb + (slot) * 1024u + 128u), "l"(s0 + HV));  \
        }                                                                      \
        asm volatile("cp.async.commit_group;");                                \
    } while (0)

__global__ __launch_bounds__(128, 8) void moe_gate_kernel(
    const float4* __restrict__ hid,
    float* __restrict__ out,
    int n_tokens)
{
    // per-warp ring: [warp][stage][token-in-warp][j]  (1KB per stage)
    __shared__ float4 ring[4][NSTAGE][8][8];     // 16 KB
    __shared__ float  part[2][HSPLIT][8][NEXP];

    const int lane = threadIdx.x & 31;
    const int w    = threadIdx.x >> 5;   // 0..3
    const int tw   = w >> 1;             // token warp 0..1 (8 tokens each)
    const int half = w & 1;              // h-half
    const int grp  = lane >> 3;          // 0..3
    const int j    = lane & 7;           // h-sub position

    const int tok_base = blockIdx.x * TOK_PER_BLOCK;
    if (tok_base >= n_tokens) return;

    const ulonglong2* gpk = (const ulonglong2*)g_packed;
    const int tile0 = half * (HHV / 8);  // 64 gate tiles per half

    // lane-fixed source base: token grp*2+0 of this warp, this half, this j
    const float4* xsrc = hid + (size_t)(tok_base + tw * 8 + grp * 2) * HV
                             + half * HHV + j;
    // lane-fixed ring destination base (stage 0, r = 0)
    const uint32_t dstb = (uint32_t)__cvta_generic_to_shared(
                              &ring[w][0][grp * 2][j]);
    // lane-fixed read pointer (stage stride = 64 float4, token stride = 8)
    const float4* rp = &ring[w][0][grp * 2][j];

    uint64_t acc[2][4];
    #pragma unroll
    for (int t = 0; t < 2; t++)
        #pragma unroll
        for (int ep = 0; ep < 4; ep++)
            acc[t][ep] = 0ull;

    // prologue: fill stages 0..2 with chunks 0..2 (groups 0..2)
    #pragma unroll
    for (int s = 0; s < NSTAGE - 1; s++)
        ISSUE(s, s);

    #pragma unroll 1
    for (int it = 0; it < ITERS; it++) {
        // group 'it' complete when <= NSTAGE-2 groups pending
        asm volatile("cp.async.wait_group %0;" :: "n"(NSTAGE - 2));

        const int sl = it & (NSTAGE - 1);
        const float4 xv0 = rp[sl * 64];      // this lane's own copies
        const float4 xv1 = rp[sl * 64 + 8];
        COMPUTE(xv0, xv1, it);

        ISSUE((it + NSTAGE - 1) & (NSTAGE - 1), it + NSTAGE - 1);
    }

    // reduce over the 8 j-lanes of each grp (masks 1,2,4 stay within the grp)
    #pragma unroll
    for (int t = 0; t < 2; t++)
        #pragma unroll
        for (int ep = 0; ep < 4; ep++) {
            uint64_t v = acc[t][ep], o;
            o = __shfl_xor_sync(0xffffffffu, (unsigned long long)v, 1); ADD2(v, v, o);
            o = __shfl_xor_sync(0xffffffffu, (unsigned long long)v, 2); ADD2(v, v, o);
            o = __shfl_xor_sync(0xffffffffu, (unsigned long long)v, 4); ADD2(v, v, o);
            acc[t][ep] = v;
        }

    if (j == 0) {
        #pragma unroll
        for (int t = 0; t < 2; t++)
            #pragma unroll
            for (int ep = 0; ep < 4; ep++) {
                unsigned lo, hi;
                UNPACK2(lo, hi, acc[t][ep]);
                part[tw][half][grp * 2 + t][2 * ep + 0] = __uint_as_float(lo);
                part[tw][half][grp * 2 + t][2 * ep + 1] = __uint_as_float(hi);
            }
    }
    __syncthreads();

    // finalize: half-0 warps, lanes 0..7 -> one token each
    if (half == 0 && lane < 8) {
        const int token = tok_base + tw * 8 + lane;

        float l[NEXP];
        #pragma unroll
        for (int q = 0; q < NEXP; q++)
            l[q] = part[tw][0][lane][q] + part[tw][1][lane][q];

        // top-1 (strict > keeps lowest index on ties, matching lax.top_k)
        float b0 = l[0]; int i0 = 0;
        #pragma unroll
        for (int q = 1; q < NEXP; q++)
            if (l[q] > b0) { b0 = l[q]; i0 = q; }

        // top-2
        float b1 = -FLT_MAX; int i1 = 0;
        #pragma unroll
        for (int q = 0; q < NEXP; q++)
            if (q != i0 && l[q] > b1) { b1 = l[q]; i1 = q; }

        // renormalized top-2 softmax: w0 = e^{l0} / (e^{l0} + e^{l1})
        const float w0 = 1.0f / (1.0f + expf(b1 - b0));
        const float w1 = 1.0f - w0;

        float* out_idx = out + (size_t)n_tokens * 2;
        out[token * 2 + 0] = w0;
        out[token * 2 + 1] = w1;
        out_idx[token * 2 + 0] = (float)i0;
        out_idx[token * 2 + 1] = (float)i1;
    }
}

extern "C" void kernel_launch(void* const* d_in, const int* in_sizes, int n_in,
                              void* d_out, int out_size)
{
    const float* hid  = (const float*)d_in[0];   // hidden_states
    const float* gate = (const float*)d_in[1];   // gate_weight
    float* out = (float*)d_out;

    const int n_tokens = in_sizes[0] / HDIM;     // 16384

    pack_gate_kernel<<<(NTILES * 64 + 255) / 256, 256>>>(gate);

    const int blocks = (n_tokens + TOK_PER_BLOCK - 1) / TOK_PER_BLOCK;  // 1024
    moe_gate_kernel<<<blocks, 128>>>((const float4*)hid, out, n_tokens);
}

// round 15
// speedup vs baseline: 1.2714x; 1.1542x over previous
#include <cuda_runtime.h>
#include <math.h>
#include <float.h>
#include <stdint.h>

// MoE gate: logits = hidden @ gate^T ; softmax over 8 experts; top-2; renormalize.
// hidden: [T, 4096] f32 (T = 16384), gate: [8, 4096] f32.
// Output (flattened f32): [T*2] topk weights, then [T*2] expert indices (as float).
//
// L1-wavefront-budget design (R12, re-bench after infra failure):
//  - 16 tokens/warp: halves gate traffic per x byte.
//  - gate goes through per-warp cp.async smem rings and is read via LDS; the
//    smem crossbar DEDUPS the 4-way broadcast across lane groups (1 wavefront)
//    where the L1 LDG path charged 4.
//  - x in per-warp cp.async rings, depth 3, no block barriers in the main loop
//    (issuer lane == reader lane; wait_group + syncwarp only).
//  - 24 L1 wavefronts per KB of x vs 48 (R9) / 40 (R7) -> ceiling ~7 TB/s.

#define NEXP   8
#define HDIM   4096
#define HV     (HDIM / 4)      // 1024 float4 per row
#define HSPLIT 2
#define HHV    (HV / HSPLIT)   // 512 float4 per half
#define ITERS  (HHV / 8)       // 64 iters (8 float4 of h per half per iter)
#define NTILES (HV / 8)        // 128 one-KB gate tiles
#define TOK_PER_BLOCK 16
#define NSTAGE 3               // ring depth (x: 2KB/stage, gate: 1KB/stage)

// Packed gate: tile t (8 float4 of h), chunk c = i*8+j = float4 of expert values
//   s = i>>1, epb = (i&1)*2, h = (t*8+j)*4 + s
//   chunk = ( g[2epb][h], g[2epb+1][h], g[2epb+2][h], g[2epb+3][h] )
__device__ float4 g_packed[NTILES * 64];   // 128 KB

__global__ void pack_gate_kernel(const float* __restrict__ gate)
{
    const int tid = blockIdx.x * blockDim.x + threadIdx.x;
    if (tid >= NTILES * 64) return;
    const int t = tid >> 6, r = tid & 63, i = r >> 3, j = r & 7;
    const int s = i >> 1, epb = (i & 1) * 2;
    const int h = (t * 8 + j) * 4 + s;
    float4 v;
    v.x = gate[(2 * epb + 0) * HDIM + h];
    v.y = gate[(2 * epb + 1) * HDIM + h];
    v.z = gate[(2 * epb + 2) * HDIM + h];
    v.w = gate[(2 * epb + 3) * HDIM + h];
    g_packed[t * 64 + i * 8 + j] = v;
}

#define FMA2(acc, a, b) \
    asm("fma.rn.f32x2 %0, %1, %2, %0;" : "+l"(acc) : "l"(a), "l"(b))
#define ADD2(d, a, b) \
    asm("add.rn.f32x2 %0, %1, %2;" : "=l"(d) : "l"(a), "l"(b))
#define PACK_DUP2(o, f) \
    asm("mov.b64 %0, {%1, %1};" : "=l"(o) : "r"(__float_as_uint(f)))
#define UNPACK2(lo, hi, v) \
    asm("mov.b64 {%0, %1}, %2;" : "=r"(lo), "=r"(hi) : "l"(v))
#define CP16(dst, src) \
    asm volatile("cp.async.cg.shared.global [%0], [%1], 16;" :: "r"(dst), "l"(src))

// Issue chunk 'itc' (x: 2KB = 16 tokens x 128B of h; gate: 1KB = tile itc)
// into ring stage 'slot'. Lane (grp,j): x -> its 4 tokens at its j (issuer ==
// reader); gate -> chunks lane, lane+32 (contiguous 512B per cp, no dup).
// Commit is UNCONDITIONAL so per-thread group numbering stays: group g == chunk g.
#define ISSUE(slot, itc)                                                     \
    do {                                                                     \
        if ((itc) < ITERS) {                                                 \
            const float4* xs_ = xs + (size_t)(itc) * 8;                      \
            const uint32_t bx = dx + (uint32_t)(slot) * 2048u;               \
            CP16(bx + 0u * 128u, xs_ + 0 * HV);                              \
            CP16(bx + 1u * 128u, xs_ + 1 * HV);                              \
            CP16(bx + 2u * 128u, xs_ + 2 * HV);                              \
            CP16(bx + 3u * 128u, xs_ + 3 * HV);                              \
            const float4* gs_ = gs + (size_t)(itc) * 64;                     \
            const uint32_t bg = dg + (uint32_t)(slot) * 1024u;               \
            CP16(bg, gs_);                                                   \
            CP16(bg + 512u, gs_ + 32);                                       \
        }                                                                    \
        asm volatile("cp.async.commit_group;");                              \
    } while (0)

__global__ __launch_bounds__(64) void moe_gate_kernel(
    const float4* __restrict__ hid,
    float* __restrict__ out,
    int n_tokens)
{
    __shared__ float4 ring_x[2][NSTAGE][TOK_PER_BLOCK][8];  // 12 KB
    __shared__ float4 ring_g[2][NSTAGE][64];                //  6 KB
    __shared__ float  part[2][TOK_PER_BLOCK][NEXP];         //  1 KB

    const int lane = threadIdx.x & 31;
    const int half = threadIdx.x >> 5;   // 0..1: h-half (both warps: same 16 tokens)
    const int grp  = lane >> 3;          // 0..3: owns tokens grp*4 .. grp*4+3
    const int j    = lane & 7;           // h-sub position

    const int tok_base = blockIdx.x * TOK_PER_BLOCK;
    if (tok_base >= n_tokens) return;

    // lane-fixed source bases
    const float4* xs = hid + (size_t)(tok_base + grp * 4) * HV + half * HHV + j;
    const float4* gs = g_packed + (size_t)(half * ITERS) * 64 + lane;

    // lane-fixed ring destinations (stage 0)
    const uint32_t dx = (uint32_t)__cvta_generic_to_shared(
                            &ring_x[half][0][grp * 4][j]);
    const uint32_t dg = (uint32_t)__cvta_generic_to_shared(
                            &ring_g[half][0][lane]);

    uint64_t acc[4][4];   // [token-in-grp][expert-pair]
    #pragma unroll
    for (int t = 0; t < 4; t++)
        #pragma unroll
        for (int ep = 0; ep < 4; ep++)
            acc[t][ep] = 0ull;

    // prologue: stages 0,1 <- chunks 0,1 (groups 0,1)
    ISSUE(0, 0);
    ISSUE(1, 1);

    int sl = 0;
    #pragma unroll 1
    for (int it = 0; it < ITERS; it++) {
        // groups issued = it+2; wait <=1 pending -> chunk 'it' complete
        asm volatile("cp.async.wait_group 1;");
        __syncwarp();   // gate chunks were written by sibling lanes

        // x: this lane's own 4 tokens at its j
        const float4 xv0 = ring_x[half][sl][grp * 4 + 0][j];
        const float4 xv1 = ring_x[half][sl][grp * 4 + 1][j];
        const float4 xv2 = ring_x[half][sl][grp * 4 + 2][j];
        const float4 xv3 = ring_x[half][sl][grp * 4 + 3][j];
        const float* xf0 = &xv0.x;
        const float* xf1 = &xv1.x;
        const float* xf2 = &xv2.x;
        const float* xf3 = &xv3.x;

        #pragma unroll
        for (int sc = 0; sc < 4; sc++) {
            // gate chunks (i=2sc, 2sc+1) at this j — smem broadcast across grps
            const ulonglong2 gA = *(const ulonglong2*)&ring_g[half][sl][16 * sc + j];
            const ulonglong2 gB = *(const ulonglong2*)&ring_g[half][sl][16 * sc + 8 + j];
            uint64_t p0, p1, p2, p3;
            PACK_DUP2(p0, xf0[sc]);
            PACK_DUP2(p1, xf1[sc]);
            PACK_DUP2(p2, xf2[sc]);
            PACK_DUP2(p3, xf3[sc]);
            FMA2(acc[0][0], p0, gA.x); FMA2(acc[0][1], p0, gA.y);
            FMA2(acc[0][2], p0, gB.x); FMA2(acc[0][3], p0, gB.y);
            FMA2(acc[1][0], p1, gA.x); FMA2(acc[1][1], p1, gA.y);
            FMA2(acc[1][2], p1, gB.x); FMA2(acc[1][3], p1, gB.y);
            FMA2(acc[2][0], p2, gA.x); FMA2(acc[2][1], p2, gA.y);
            FMA2(acc[2][2], p2, gB.x); FMA2(acc[2][3], p2, gB.y);
            FMA2(acc[3][0], p3, gA.x); FMA2(acc[3][1], p3, gA.y);
            FMA2(acc[3][2], p3, gB.x); FMA2(acc[3][3], p3, gB.y);
        }

        int isl = sl + 2; if (isl >= NSTAGE) isl -= NSTAGE;
        ISSUE(isl, it + 2);
        sl++; if (sl == NSTAGE) sl = 0;
    }

    // reduce over the 8 j-lanes of each grp (masks 1,2,4 stay within the grp)
    #pragma unroll
    for (int t = 0; t < 4; t++)
        #pragma unroll
        for (int ep = 0; ep < 4; ep++) {
            uint64_t v = acc[t][ep], o;
            o = __shfl_xor_sync(0xffffffffu, (unsigned long long)v, 1); ADD2(v, v, o);
            o = __shfl_xor_sync(0xffffffffu, (unsigned long long)v, 2); ADD2(v, v, o);
            o = __shfl_xor_sync(0xffffffffu, (unsigned long long)v, 4); ADD2(v, v, o);
            acc[t][ep] = v;
        }

    if (j == 0) {
        #pragma unroll
        for (int t = 0; t < 4; t++)
            #pragma unroll
            for (int ep = 0; ep < 4; ep++) {
                unsigned lo, hi;
                UNPACK2(lo, hi, acc[t][ep]);
                part[half][grp * 4 + t][2 * ep + 0] = __uint_as_float(lo);
                part[half][grp * 4 + t][2 * ep + 1] = __uint_as_float(hi);
            }
    }
    __syncthreads();

    // finalize: threads 0..15 -> one token each
    if (threadIdx.x < TOK_PER_BLOCK) {
        const int tid   = threadIdx.x;
        const int token = tok_base + tid;
        if (token < n_tokens) {
            float l[NEXP];
            #pragma unroll
            for (int q = 0; q < NEXP; q++)
                l[q] = part[0][tid][q] + part[1][tid][q];

            // top-1 (strict > keeps lowest index on ties, matching lax.top_k)
            float b0 = l[0]; int i0 = 0;
            #pragma unroll
            for (int q = 1; q < NEXP; q++)
                if (l[q] > b0) { b0 = l[q]; i0 = q; }

            // top-2
            float b1 = -FLT_MAX; int i1 = 0;
            #pragma unroll
            for (int q = 0; q < NEXP; q++)
                if (q != i0 && l[q] > b1) { b1 = l[q]; i1 = q; }

            // renormalized top-2 softmax: w0 = e^{l0} / (e^{l0} + e^{l1})
            const float w0 = 1.0f / (1.0f + expf(b1 - b0));
            const float w1 = 1.0f - w0;

            float* out_idx = out + (size_t)n_tokens * 2;
            out[token * 2 + 0] = w0;
            out[token * 2 + 1] = w1;
            out_idx[token * 2 + 0] = (float)i0;
            out_idx[token * 2 + 1] = (float)i1;
        }
    }
}

extern "C" void kernel_launch(void* const* d_in, const int* in_sizes, int n_in,
                              void* d_out, int out_size)
{
    const float* hid  = (const float*)d_in[0];   // hidden_states
    const float* gate = (const float*)d_in[1];   // gate_weight
    float* out = (float*)d_out;

    const int n_tokens = in_sizes[0] / HDIM;     // 16384

    pack_gate_kernel<<<(NTILES * 64 + 255) / 256, 256>>>(gate);

    const int blocks = (n_tokens + TOK_PER_BLOCK - 1) / TOK_PER_BLOCK;  // 1024
    moe_gate_kernel<<<blocks, 64>>>((const float4*)hid, out, n_tokens);
}